// round 10
// baseline (speedup 1.0000x reference)
#include <cuda_runtime.h>
#include <cuda_bf16.h>
#include <cstdint>

// Fused 3-layer MLP + action masking.
// B=65536 rows, dims 256 -> 256 -> 256 -> 128, fp32.
// One CTA = 128 rows. Activations live transposed in SMEM (HT[k][r]),
// weights stream through SMEM in 64-row K chunks. Each thread owns an
// 8x8 (layers 1,2) / 8x4 (layer 3) register accumulator tile.

#define BM        128
#define NTHREADS  512
#define HT_STRIDE 132   // 128 rows + 4 pad floats (bank-conflict mitigation)
#define KC        64    // K-chunk rows of W staged in SMEM
#define FLOAT_LOWEST (-3.402823466385288598e+38f)

__device__ __forceinline__ float relu_f(float x) { return x > 0.0f ? x : 0.0f; }

// One GEMM layer: acc[8][CPT] += HT(128 x 256, transposed)^T-slice @ W(256 x N)
// N = 256 (CPT=8) or 128 (CPT=4). Starts with __syncthreads() (guards HT/WS reuse).
template <int N, int CPT>
__device__ __forceinline__ void mma_layer(
    const float* __restrict__ HT, float* __restrict__ WS,
    const float* __restrict__ Wg,
    float (&acc)[8][CPT], int tid, int tr, int tc)
{
#pragma unroll
    for (int i = 0; i < 8; ++i)
#pragma unroll
        for (int j = 0; j < CPT; ++j) acc[i][j] = 0.0f;

    const int r0 = tr * 8;

    for (int kc = 0; kc < 256; kc += KC) {
        __syncthreads();   // prior readers of WS / writers of HT done
        {
            const float4* src = (const float4*)(Wg + (size_t)kc * N);
            float4* dst = (float4*)WS;
            const int nv = KC * N / 4;
#pragma unroll
            for (int i = tid; i < nv; i += NTHREADS) dst[i] = src[i];
        }
        __syncthreads();

#pragma unroll 4
        for (int kk = 0; kk < KC; ++kk) {
            const float* hrow = HT + (kc + kk) * HT_STRIDE + r0;
            float4 xa = *(const float4*)(hrow);
            float4 xb = *(const float4*)(hrow + 4);
            float xf[8] = {xa.x, xa.y, xa.z, xa.w, xb.x, xb.y, xb.z, xb.w};

            const float* wrow = WS + kk * N + tc * CPT;
            float wf[CPT];
#pragma unroll
            for (int q = 0; q < CPT / 4; ++q) {
                float4 w = *(const float4*)(wrow + q * 4);
                wf[q * 4 + 0] = w.x; wf[q * 4 + 1] = w.y;
                wf[q * 4 + 2] = w.z; wf[q * 4 + 3] = w.w;
            }

#pragma unroll
            for (int i = 0; i < 8; ++i)
#pragma unroll
                for (int j = 0; j < CPT; ++j)
                    acc[i][j] = fmaf(xf[i], wf[j], acc[i][j]);
        }
    }
}

// relu(acc + b) written transposed into HT[c][r] (input for next layer).
__device__ __forceinline__ void store_relu_T(
    float* __restrict__ HT, const float (&acc)[8][8],
    const float* __restrict__ bias, int tr, int tc)
{
    const int r0 = tr * 8;
#pragma unroll
    for (int j = 0; j < 8; ++j) {
        const int c = tc * 8 + j;
        const float b = __ldg(bias + c);
        float4 lo, hi;
        lo.x = relu_f(acc[0][j] + b); lo.y = relu_f(acc[1][j] + b);
        lo.z = relu_f(acc[2][j] + b); lo.w = relu_f(acc[3][j] + b);
        hi.x = relu_f(acc[4][j] + b); hi.y = relu_f(acc[5][j] + b);
        hi.z = relu_f(acc[6][j] + b); hi.w = relu_f(acc[7][j] + b);
        *(float4*)(HT + c * HT_STRIDE + r0)     = lo;
        *(float4*)(HT + c * HT_STRIDE + r0 + 4) = hi;
    }
}

__global__ __launch_bounds__(NTHREADS, 1)
void colornet_kernel(const float* __restrict__ X,
                     const int*   __restrict__ mask,
                     const float* __restrict__ W1, const float* __restrict__ b1,
                     const float* __restrict__ W2, const float* __restrict__ b2,
                     const float* __restrict__ W3, const float* __restrict__ b3,
                     float* __restrict__ out)
{
    extern __shared__ float smem[];
    float* HT   = smem;                         // [256][HT_STRIDE]
    float* WS   = smem + 256 * HT_STRIDE;       // [KC][256] max
    int*   anyv = (int*)(WS + KC * 256);        // [BM]

    const int tid = threadIdx.x;
    const int tc  = tid & 31;   // 0..31 (col-group)
    const int tr  = tid >> 5;   // 0..15 (row-group)
    const int r0  = tr * 8;
    const size_t rowBase = (size_t)blockIdx.x * BM;

    // Per-row any(mask != 0) reduction
    if (tid < BM) {
        const int4* mrow = (const int4*)(mask + (rowBase + tid) * 128);
        int any = 0;
#pragma unroll
        for (int q = 0; q < 32; ++q) {
            int4 v = __ldg(mrow + q);
            any |= v.x | v.y | v.z | v.w;
        }
        anyv[tid] = any;
    }

    // Load X tile transposed: HT[k][r] = X[rowBase + r][k]
    {
        const int kq   = tid & 63;   // k-quad: k0 = kq*4
        const int rBeg = tid >> 6;   // 0..7
#pragma unroll
        for (int rr = 0; rr < BM; rr += 8) {
            const int r = rBeg + rr;
            float4 v = *(const float4*)(X + (rowBase + r) * 256 + kq * 4);
            const int k0 = kq * 4;
            HT[(k0 + 0) * HT_STRIDE + r] = v.x;
            HT[(k0 + 1) * HT_STRIDE + r] = v.y;
            HT[(k0 + 2) * HT_STRIDE + r] = v.z;
            HT[(k0 + 3) * HT_STRIDE + r] = v.w;
        }
    }
    // (mma_layer begins with __syncthreads(), which publishes HT + anyv)

    float acc[8][8];

    // Layer 1
    mma_layer<256, 8>(HT, WS, W1, acc, tid, tr, tc);
    __syncthreads();                 // all HT reads done before overwrite
    store_relu_T(HT, acc, b1, tr, tc);

    // Layer 2
    mma_layer<256, 8>(HT, WS, W2, acc, tid, tr, tc);
    __syncthreads();
    store_relu_T(HT, acc, b2, tr, tc);

    // Layer 3 (N = A = 128)
    float acc3[8][4];
    mma_layer<128, 4>(HT, WS, W3, acc3, tid, tr, tc);

    // Masked epilogue
    const int c0 = tc * 4;
    float bb[4];
#pragma unroll
    for (int j = 0; j < 4; ++j) bb[j] = __ldg(b3 + c0 + j);

#pragma unroll
    for (int i = 0; i < 8; ++i) {
        const int r = r0 + i;
        const size_t gr = rowBase + r;
        int4 m = __ldg((const int4*)(mask + gr * 128 + c0));
        const bool av = (anyv[r] != 0);
        float4 o;
        o.x = (m.x != 0) ? (acc3[i][0] + bb[0]) : FLOAT_LOWEST;
        o.y = (m.y != 0) ? (acc3[i][1] + bb[1]) : FLOAT_LOWEST;
        o.z = (m.z != 0) ? (acc3[i][2] + bb[2]) : FLOAT_LOWEST;
        o.w = (m.w != 0) ? (acc3[i][3] + bb[3]) : FLOAT_LOWEST;
        if (!av) {
            o.x = (c0 == 0) ? 1.0f : FLOAT_LOWEST;
            o.y = FLOAT_LOWEST; o.z = FLOAT_LOWEST; o.w = FLOAT_LOWEST;
        }
        *(float4*)(out + gr * 128 + c0) = o;
    }
}

extern "C" void kernel_launch(void* const* d_in, const int* in_sizes, int n_in,
                              void* d_out, int out_size)
{
    const float* X    = (const float*)d_in[0];
    const int*   mask = (const int*)d_in[1];
    const float* W1   = (const float*)d_in[2];
    const float* b1   = (const float*)d_in[3];
    const float* W2   = (const float*)d_in[4];
    const float* b2   = (const float*)d_in[5];
    const float* W3   = (const float*)d_in[6];
    const float* b3   = (const float*)d_in[7];
    float* out = (float*)d_out;

    const int B    = in_sizes[0] / 256;   // 65536
    const int grid = B / BM;              // 512

    const size_t smem_bytes =
        (size_t)(256 * HT_STRIDE + KC * 256) * sizeof(float) + BM * sizeof(int);

    cudaFuncSetAttribute(colornet_kernel,
                         cudaFuncAttributeMaxDynamicSharedMemorySize,
                         (int)smem_bytes);

    colornet_kernel<<<grid, NTHREADS, smem_bytes>>>(
        X, mask, W1, b1, W2, b2, W3, b3, out);
}

// round 11
// speedup vs baseline: 1.0044x; 1.0044x over previous
#include <cuda_runtime.h>
#include <cuda_bf16.h>
#include <cstdint>

// Fused 3-layer MLP + action masking.
// B=65536 rows, dims 256 -> 256 -> 256 -> 128, fp32.
// One CTA = 128 rows. Activations live transposed in SMEM (HT[k][r]),
// weights stream through SMEM in 64-row K chunks. Each thread owns an
// 8x8 (layers 1,2) / 8x4 (layer 3) register accumulator tile.

#define BM        128
#define NTHREADS  512
#define HT_STRIDE 132   // 128 rows + 4 pad floats (bank-conflict mitigation)
#define KC        64    // K-chunk rows of W staged in SMEM
#define FLOAT_LOWEST (-3.402823466385288598e+38f)

__device__ __forceinline__ float relu_f(float x) { return x > 0.0f ? x : 0.0f; }

// One GEMM layer: acc[8][CPT] += HT(128 x 256, transposed)^T-slice @ W(256 x N)
// N = 256 (CPT=8) or 128 (CPT=4). Starts with __syncthreads() (guards HT/WS reuse).
template <int N, int CPT>
__device__ __forceinline__ void mma_layer(
    const float* __restrict__ HT, float* __restrict__ WS,
    const float* __restrict__ Wg,
    float (&acc)[8][CPT], int tid, int tr, int tc)
{
#pragma unroll
    for (int i = 0; i < 8; ++i)
#pragma unroll
        for (int j = 0; j < CPT; ++j) acc[i][j] = 0.0f;

    const int r0 = tr * 8;

    for (int kc = 0; kc < 256; kc += KC) {
        __syncthreads();   // prior readers of WS / writers of HT done
        {
            const float4* src = (const float4*)(Wg + (size_t)kc * N);
            float4* dst = (float4*)WS;
            const int nv = KC * N / 4;
#pragma unroll
            for (int i = tid; i < nv; i += NTHREADS) dst[i] = src[i];
        }
        __syncthreads();

#pragma unroll 4
        for (int kk = 0; kk < KC; ++kk) {
            const float* hrow = HT + (kc + kk) * HT_STRIDE + r0;
            float4 xa = *(const float4*)(hrow);
            float4 xb = *(const float4*)(hrow + 4);
            float xf[8] = {xa.x, xa.y, xa.z, xa.w, xb.x, xb.y, xb.z, xb.w};

            const float* wrow = WS + kk * N + tc * CPT;
            float wf[CPT];
#pragma unroll
            for (int q = 0; q < CPT / 4; ++q) {
                float4 w = *(const float4*)(wrow + q * 4);
                wf[q * 4 + 0] = w.x; wf[q * 4 + 1] = w.y;
                wf[q * 4 + 2] = w.z; wf[q * 4 + 3] = w.w;
            }

#pragma unroll
            for (int i = 0; i < 8; ++i)
#pragma unroll
                for (int j = 0; j < CPT; ++j)
                    acc[i][j] = fmaf(xf[i], wf[j], acc[i][j]);
        }
    }
}

// relu(acc + b) written transposed into HT[c][r] (input for next layer).
__device__ __forceinline__ void store_relu_T(
    float* __restrict__ HT, const float (&acc)[8][8],
    const float* __restrict__ bias, int tr, int tc)
{
    const int r0 = tr * 8;
#pragma unroll
    for (int j = 0; j < 8; ++j) {
        const int c = tc * 8 + j;
        const float b = __ldg(bias + c);
        float4 lo, hi;
        lo.x = relu_f(acc[0][j] + b); lo.y = relu_f(acc[1][j] + b);
        lo.z = relu_f(acc[2][j] + b); lo.w = relu_f(acc[3][j] + b);
        hi.x = relu_f(acc[4][j] + b); hi.y = relu_f(acc[5][j] + b);
        hi.z = relu_f(acc[6][j] + b); hi.w = relu_f(acc[7][j] + b);
        *(float4*)(HT + c * HT_STRIDE + r0)     = lo;
        *(float4*)(HT + c * HT_STRIDE + r0 + 4) = hi;
    }
}

__global__ __launch_bounds__(NTHREADS, 1)
void colornet_kernel(const float* __restrict__ X,
                     const int*   __restrict__ mask,
                     const float* __restrict__ W1, const float* __restrict__ b1,
                     const float* __restrict__ W2, const float* __restrict__ b2,
                     const float* __restrict__ W3, const float* __restrict__ b3,
                     float* __restrict__ out)
{
    extern __shared__ float smem[];
    float* HT   = smem;                         // [256][HT_STRIDE]
    float* WS   = smem + 256 * HT_STRIDE;       // [KC][256] max
    int*   anyv = (int*)(WS + KC * 256);        // [BM]

    const int tid = threadIdx.x;
    const int tc  = tid & 31;   // 0..31 (col-group)
    const int tr  = tid >> 5;   // 0..15 (row-group)
    const int r0  = tr * 8;
    const size_t rowBase = (size_t)blockIdx.x * BM;

    // Per-row any(mask != 0) reduction
    if (tid < BM) {
        const int4* mrow = (const int4*)(mask + (rowBase + tid) * 128);
        int any = 0;
#pragma unroll
        for (int q = 0; q < 32; ++q) {
            int4 v = __ldg(mrow + q);
            any |= v.x | v.y | v.z | v.w;
        }
        anyv[tid] = any;
    }

    // Load X tile transposed: HT[k][r] = X[rowBase + r][k]
    {
        const int kq   = tid & 63;   // k-quad: k0 = kq*4
        const int rBeg = tid >> 6;   // 0..7
#pragma unroll
        for (int rr = 0; rr < BM; rr += 8) {
            const int r = rBeg + rr;
            float4 v = *(const float4*)(X + (rowBase + r) * 256 + kq * 4);
            const int k0 = kq * 4;
            HT[(k0 + 0) * HT_STRIDE + r] = v.x;
            HT[(k0 + 1) * HT_STRIDE + r] = v.y;
            HT[(k0 + 2) * HT_STRIDE + r] = v.z;
            HT[(k0 + 3) * HT_STRIDE + r] = v.w;
        }
    }
    // (mma_layer begins with __syncthreads(), which publishes HT + anyv)

    float acc[8][8];

    // Layer 1
    mma_layer<256, 8>(HT, WS, W1, acc, tid, tr, tc);
    __syncthreads();                 // all HT reads done before overwrite
    store_relu_T(HT, acc, b1, tr, tc);

    // Layer 2
    mma_layer<256, 8>(HT, WS, W2, acc, tid, tr, tc);
    __syncthreads();
    store_relu_T(HT, acc, b2, tr, tc);

    // Layer 3 (N = A = 128)
    float acc3[8][4];
    mma_layer<128, 4>(HT, WS, W3, acc3, tid, tr, tc);

    // Masked epilogue
    const int c0 = tc * 4;
    float bb[4];
#pragma unroll
    for (int j = 0; j < 4; ++j) bb[j] = __ldg(b3 + c0 + j);

#pragma unroll
    for (int i = 0; i < 8; ++i) {
        const int r = r0 + i;
        const size_t gr = rowBase + r;
        int4 m = __ldg((const int4*)(mask + gr * 128 + c0));
        const bool av = (anyv[r] != 0);
        float4 o;
        o.x = (m.x != 0) ? (acc3[i][0] + bb[0]) : FLOAT_LOWEST;
        o.y = (m.y != 0) ? (acc3[i][1] + bb[1]) : FLOAT_LOWEST;
        o.z = (m.z != 0) ? (acc3[i][2] + bb[2]) : FLOAT_LOWEST;
        o.w = (m.w != 0) ? (acc3[i][3] + bb[3]) : FLOAT_LOWEST;
        if (!av) {
            o.x = (c0 == 0) ? 1.0f : FLOAT_LOWEST;
            o.y = FLOAT_LOWEST; o.z = FLOAT_LOWEST; o.w = FLOAT_LOWEST;
        }
        *(float4*)(out + gr * 128 + c0) = o;
    }
}

extern "C" void kernel_launch(void* const* d_in, const int* in_sizes, int n_in,
                              void* d_out, int out_size)
{
    const float* X    = (const float*)d_in[0];
    const int*   mask = (const int*)d_in[1];
    const float* W1   = (const float*)d_in[2];
    const float* b1   = (const float*)d_in[3];
    const float* W2   = (const float*)d_in[4];
    const float* b2   = (const float*)d_in[5];
    const float* W3   = (const float*)d_in[6];
    const float* b3   = (const float*)d_in[7];
    float* out = (float*)d_out;

    const int B    = in_sizes[0] / 256;   // 65536
    const int grid = B / BM;              // 512

    const size_t smem_bytes =
        (size_t)(256 * HT_STRIDE + KC * 256) * sizeof(float) + BM * sizeof(int);

    cudaFuncSetAttribute(colornet_kernel,
                         cudaFuncAttributeMaxDynamicSharedMemorySize,
                         (int)smem_bytes);

    colornet_kernel<<<grid, NTHREADS, smem_bytes>>>(
        X, mask, W1, b1, W2, b2, W3, b3, out);
}

// round 12
// speedup vs baseline: 1.0054x; 1.0010x over previous
#include <cuda_runtime.h>
#include <cuda_bf16.h>
#include <cstdint>

// Fused 3-layer MLP + action masking.
// B=65536 rows, dims 256 -> 256 -> 256 -> 128, fp32.
// One CTA = 128 rows. Activations live transposed in SMEM (HT[k][r]),
// weights stream through SMEM in 64-row K chunks. Each thread owns an
// 8x8 (layers 1,2) / 8x4 (layer 3) register accumulator tile.

#define BM        128
#define NTHREADS  512
#define HT_STRIDE 132   // 128 rows + 4 pad floats (bank-conflict mitigation)
#define KC        64    // K-chunk rows of W staged in SMEM
#define FLOAT_LOWEST (-3.402823466385288598e+38f)

__device__ __forceinline__ float relu_f(float x) { return x > 0.0f ? x : 0.0f; }

// One GEMM layer: acc[8][CPT] += HT(128 x 256, transposed)^T-slice @ W(256 x N)
// N = 256 (CPT=8) or 128 (CPT=4). Starts with __syncthreads() (guards HT/WS reuse).
template <int N, int CPT>
__device__ __forceinline__ void mma_layer(
    const float* __restrict__ HT, float* __restrict__ WS,
    const float* __restrict__ Wg,
    float (&acc)[8][CPT], int tid, int tr, int tc)
{
#pragma unroll
    for (int i = 0; i < 8; ++i)
#pragma unroll
        for (int j = 0; j < CPT; ++j) acc[i][j] = 0.0f;

    const int r0 = tr * 8;

    for (int kc = 0; kc < 256; kc += KC) {
        __syncthreads();   // prior readers of WS / writers of HT done
        {
            const float4* src = (const float4*)(Wg + (size_t)kc * N);
            float4* dst = (float4*)WS;
            const int nv = KC * N / 4;
#pragma unroll
            for (int i = tid; i < nv; i += NTHREADS) dst[i] = src[i];
        }
        __syncthreads();

#pragma unroll 4
        for (int kk = 0; kk < KC; ++kk) {
            const float* hrow = HT + (kc + kk) * HT_STRIDE + r0;
            float4 xa = *(const float4*)(hrow);
            float4 xb = *(const float4*)(hrow + 4);
            float xf[8] = {xa.x, xa.y, xa.z, xa.w, xb.x, xb.y, xb.z, xb.w};

            const float* wrow = WS + kk * N + tc * CPT;
            float wf[CPT];
#pragma unroll
            for (int q = 0; q < CPT / 4; ++q) {
                float4 w = *(const float4*)(wrow + q * 4);
                wf[q * 4 + 0] = w.x; wf[q * 4 + 1] = w.y;
                wf[q * 4 + 2] = w.z; wf[q * 4 + 3] = w.w;
            }

#pragma unroll
            for (int i = 0; i < 8; ++i)
#pragma unroll
                for (int j = 0; j < CPT; ++j)
                    acc[i][j] = fmaf(xf[i], wf[j], acc[i][j]);
        }
    }
}

// relu(acc + b) written transposed into HT[c][r] (input for next layer).
__device__ __forceinline__ void store_relu_T(
    float* __restrict__ HT, const float (&acc)[8][8],
    const float* __restrict__ bias, int tr, int tc)
{
    const int r0 = tr * 8;
#pragma unroll
    for (int j = 0; j < 8; ++j) {
        const int c = tc * 8 + j;
        const float b = __ldg(bias + c);
        float4 lo, hi;
        lo.x = relu_f(acc[0][j] + b); lo.y = relu_f(acc[1][j] + b);
        lo.z = relu_f(acc[2][j] + b); lo.w = relu_f(acc[3][j] + b);
        hi.x = relu_f(acc[4][j] + b); hi.y = relu_f(acc[5][j] + b);
        hi.z = relu_f(acc[6][j] + b); hi.w = relu_f(acc[7][j] + b);
        *(float4*)(HT + c * HT_STRIDE + r0)     = lo;
        *(float4*)(HT + c * HT_STRIDE + r0 + 4) = hi;
    }
}

__global__ __launch_bounds__(NTHREADS, 1)
void colornet_kernel(const float* __restrict__ X,
                     const int*   __restrict__ mask,
                     const float* __restrict__ W1, const float* __restrict__ b1,
                     const float* __restrict__ W2, const float* __restrict__ b2,
                     const float* __restrict__ W3, const float* __restrict__ b3,
                     float* __restrict__ out)
{
    extern __shared__ float smem[];
    float* HT   = smem;                         // [256][HT_STRIDE]
    float* WS   = smem + 256 * HT_STRIDE;       // [KC][256] max
    int*   anyv = (int*)(WS + KC * 256);        // [BM]

    const int tid = threadIdx.x;
    const int tc  = tid & 31;   // 0..31 (col-group)
    const int tr  = tid >> 5;   // 0..15 (row-group)
    const int r0  = tr * 8;
    const size_t rowBase = (size_t)blockIdx.x * BM;

    // Per-row any(mask != 0) reduction
    if (tid < BM) {
        const int4* mrow = (const int4*)(mask + (rowBase + tid) * 128);
        int any = 0;
#pragma unroll
        for (int q = 0; q < 32; ++q) {
            int4 v = __ldg(mrow + q);
            any |= v.x | v.y | v.z | v.w;
        }
        anyv[tid] = any;
    }

    // Load X tile transposed: HT[k][r] = X[rowBase + r][k]
    {
        const int kq   = tid & 63;   // k-quad: k0 = kq*4
        const int rBeg = tid >> 6;   // 0..7
#pragma unroll
        for (int rr = 0; rr < BM; rr += 8) {
            const int r = rBeg + rr;
            float4 v = *(const float4*)(X + (rowBase + r) * 256 + kq * 4);
            const int k0 = kq * 4;
            HT[(k0 + 0) * HT_STRIDE + r] = v.x;
            HT[(k0 + 1) * HT_STRIDE + r] = v.y;
            HT[(k0 + 2) * HT_STRIDE + r] = v.z;
            HT[(k0 + 3) * HT_STRIDE + r] = v.w;
        }
    }
    // (mma_layer begins with __syncthreads(), which publishes HT + anyv)

    float acc[8][8];

    // Layer 1
    mma_layer<256, 8>(HT, WS, W1, acc, tid, tr, tc);
    __syncthreads();                 // all HT reads done before overwrite
    store_relu_T(HT, acc, b1, tr, tc);

    // Layer 2
    mma_layer<256, 8>(HT, WS, W2, acc, tid, tr, tc);
    __syncthreads();
    store_relu_T(HT, acc, b2, tr, tc);

    // Layer 3 (N = A = 128)
    float acc3[8][4];
    mma_layer<128, 4>(HT, WS, W3, acc3, tid, tr, tc);

    // Masked epilogue
    const int c0 = tc * 4;
    float bb[4];
#pragma unroll
    for (int j = 0; j < 4; ++j) bb[j] = __ldg(b3 + c0 + j);

#pragma unroll
    for (int i = 0; i < 8; ++i) {
        const int r = r0 + i;
        const size_t gr = rowBase + r;
        int4 m = __ldg((const int4*)(mask + gr * 128 + c0));
        const bool av = (anyv[r] != 0);
        float4 o;
        o.x = (m.x != 0) ? (acc3[i][0] + bb[0]) : FLOAT_LOWEST;
        o.y = (m.y != 0) ? (acc3[i][1] + bb[1]) : FLOAT_LOWEST;
        o.z = (m.z != 0) ? (acc3[i][2] + bb[2]) : FLOAT_LOWEST;
        o.w = (m.w != 0) ? (acc3[i][3] + bb[3]) : FLOAT_LOWEST;
        if (!av) {
            o.x = (c0 == 0) ? 1.0f : FLOAT_LOWEST;
            o.y = FLOAT_LOWEST; o.z = FLOAT_LOWEST; o.w = FLOAT_LOWEST;
        }
        *(float4*)(out + gr * 128 + c0) = o;
    }
}

extern "C" void kernel_launch(void* const* d_in, const int* in_sizes, int n_in,
                              void* d_out, int out_size)
{
    const float* X    = (const float*)d_in[0];
    const int*   mask = (const int*)d_in[1];
    const float* W1   = (const float*)d_in[2];
    const float* b1   = (const float*)d_in[3];
    const float* W2   = (const float*)d_in[4];
    const float* b2   = (const float*)d_in[5];
    const float* W3   = (const float*)d_in[6];
    const float* b3   = (const float*)d_in[7];
    float* out = (float*)d_out;

    const int B    = in_sizes[0] / 256;   // 65536
    const int grid = B / BM;              // 512

    const size_t smem_bytes =
        (size_t)(256 * HT_STRIDE + KC * 256) * sizeof(float) + BM * sizeof(int);

    cudaFuncSetAttribute(colornet_kernel,
                         cudaFuncAttributeMaxDynamicSharedMemorySize,
                         (int)smem_bytes);

    colornet_kernel<<<grid, NTHREADS, smem_bytes>>>(
        X, mask, W1, b1, W2, b2, W3, b3, out);
}